// round 6
// baseline (speedup 1.0000x reference)
#include <cuda_runtime.h>
#include <math.h>

#define B_SZ 64
#define N_SZ 4096
#define D_SZ 256
#define TEMPERATURE 0.1f
#define EPS 1e-8f

__global__ __launch_bounds__(1024, 1)
void graph_contrastive_loss_kernel(const float* __restrict__ emb,
                                   const int* __restrict__ anchor_idx,
                                   const int* __restrict__ pos_idx,
                                   const int* __restrict__ neg_graph_idx,
                                   const int* __restrict__ neg_node_idx,
                                   float* __restrict__ out) {
    const int warp = threadIdx.x >> 5;
    const int lane = threadIdx.x & 31;
    __shared__ float per_sample[B_SZ];

    // 32 warps, 64 samples -> each warp handles s = warp and s = warp + 32
    #pragma unroll
    for (int rep = 0; rep < 2; ++rep) {
        const int s = warp + rep * 32;
        const int ai = anchor_idx[s];
        const int pi = pos_idx[s];
        const int ng = neg_graph_idx[s];
        const int ni = neg_node_idx[s];

        const float4* A = reinterpret_cast<const float4*>(
            emb + ((size_t)s * N_SZ + ai) * D_SZ);
        const float4* P = reinterpret_cast<const float4*>(
            emb + ((size_t)s * N_SZ + pi) * D_SZ);
        const float4* Ng = reinterpret_cast<const float4*>(
            emb + ((size_t)ng * N_SZ + ni) * D_SZ);

        float ap = 0.f, an = 0.f, aa = 0.f, pp = 0.f, nn = 0.f;
        // D=256 floats = 64 float4; 32 lanes -> 2 float4 per lane per vector
        #pragma unroll
        for (int i = 0; i < 2; ++i) {
            const int idx = lane + 32 * i;
            const float4 av = A[idx];
            const float4 pv = P[idx];
            const float4 nv = Ng[idx];
            ap += av.x * pv.x + av.y * pv.y + av.z * pv.z + av.w * pv.w;
            an += av.x * nv.x + av.y * nv.y + av.z * nv.z + av.w * nv.w;
            aa += av.x * av.x + av.y * av.y + av.z * av.z + av.w * av.w;
            pp += pv.x * pv.x + pv.y * pv.y + pv.z * pv.z + pv.w * pv.w;
            nn += nv.x * nv.x + nv.y * nv.y + nv.z * nv.z + nv.w * nv.w;
        }

        // warp-level tree reduction of the 5 partial sums
        #pragma unroll
        for (int off = 16; off > 0; off >>= 1) {
            ap += __shfl_down_sync(0xFFFFFFFFu, ap, off);
            an += __shfl_down_sync(0xFFFFFFFFu, an, off);
            aa += __shfl_down_sync(0xFFFFFFFFu, aa, off);
            pp += __shfl_down_sync(0xFFFFFFFFu, pp, off);
            nn += __shfl_down_sync(0xFFFFFFFFu, nn, off);
        }

        if (lane == 0) {
            const float na = fmaxf(sqrtf(aa), EPS);
            const float np = fmaxf(sqrtf(pp), EPS);
            const float nq = fmaxf(sqrtf(nn), EPS);
            const float pos_sim = (ap / (na * np)) / TEMPERATURE;
            const float neg_sim = (an / (na * nq)) / TEMPERATURE;
            const float d = neg_sim - pos_sim;
            // logaddexp(0, d), numerically stable
            per_sample[s] = fmaxf(d, 0.f) + log1pf(expf(-fabsf(d)));
        }
    }

    __syncthreads();

    // final mean over 64 values: warp 0 only, fixed deterministic order
    if (warp == 0) {
        float v = per_sample[lane] + per_sample[lane + 32];
        #pragma unroll
        for (int off = 16; off > 0; off >>= 1)
            v += __shfl_down_sync(0xFFFFFFFFu, v, off);
        if (lane == 0)
            out[0] = v * (1.0f / (float)B_SZ);
    }
}

extern "C" void kernel_launch(void* const* d_in, const int* in_sizes, int n_in,
                              void* d_out, int out_size) {
    const float* emb           = (const float*)d_in[0];
    // d_in[1] = graph_labels (unused by the loss)
    const int*   anchor_idx    = (const int*)d_in[2];
    const int*   pos_idx       = (const int*)d_in[3];
    const int*   neg_graph_idx = (const int*)d_in[4];
    const int*   neg_node_idx  = (const int*)d_in[5];
    float*       out           = (float*)d_out;

    graph_contrastive_loss_kernel<<<1, 1024>>>(
        emb, anchor_idx, pos_idx, neg_graph_idx, neg_node_idx, out);
}

// round 7
// speedup vs baseline: 1.3659x; 1.3659x over previous
#include <cuda_runtime.h>
#include <math.h>

#define B_SZ 64
#define N_SZ 4096
#define D_SZ 256
#define TEMPERATURE 0.1f
#define EPS 1e-8f

// Cross-block reduction scratch (no allocation allowed -> device globals).
__device__ float g_per_sample[B_SZ];
__device__ int   g_counter = 0;   // reset to 0 by the last block each run

__global__ __launch_bounds__(64, 1)
void graph_contrastive_loss_kernel(const float* __restrict__ emb,
                                   const int* __restrict__ anchor_idx,
                                   const int* __restrict__ pos_idx,
                                   const int* __restrict__ neg_graph_idx,
                                   const int* __restrict__ neg_node_idx,
                                   float* __restrict__ out) {
    const int s    = blockIdx.x;      // one sample per block
    const int t    = threadIdx.x;     // 0..63
    const int lane = t & 31;
    const int warp = t >> 5;          // 0 or 1

    __shared__ float red[2][5];
    __shared__ int   is_last;

    // Index loads: all threads hit the same 4 addresses -> broadcast requests.
    const int ai = __ldg(anchor_idx + s);
    const int pi = __ldg(pos_idx + s);
    const int ng = __ldg(neg_graph_idx + s);
    const int ni = __ldg(neg_node_idx + s);

    const float4* A  = reinterpret_cast<const float4*>(
        emb + ((size_t)s  * N_SZ + ai) * D_SZ);
    const float4* P  = reinterpret_cast<const float4*>(
        emb + ((size_t)s  * N_SZ + pi) * D_SZ);
    const float4* Ng = reinterpret_cast<const float4*>(
        emb + ((size_t)ng * N_SZ + ni) * D_SZ);

    // D=256 floats = 64 float4; 64 threads -> exactly 1 float4 per vector per thread.
    const float4 av = A[t];
    const float4 pv = P[t];
    const float4 nv = Ng[t];

    float ap = av.x * pv.x + av.y * pv.y + av.z * pv.z + av.w * pv.w;
    float an = av.x * nv.x + av.y * nv.y + av.z * nv.z + av.w * nv.w;
    float aa = av.x * av.x + av.y * av.y + av.z * av.z + av.w * av.w;
    float pp = pv.x * pv.x + pv.y * pv.y + pv.z * pv.z + pv.w * pv.w;
    float nn = nv.x * nv.x + nv.y * nv.y + nv.z * nv.z + nv.w * nv.w;

    #pragma unroll
    for (int off = 16; off > 0; off >>= 1) {
        ap += __shfl_down_sync(0xFFFFFFFFu, ap, off);
        an += __shfl_down_sync(0xFFFFFFFFu, an, off);
        aa += __shfl_down_sync(0xFFFFFFFFu, aa, off);
        pp += __shfl_down_sync(0xFFFFFFFFu, pp, off);
        nn += __shfl_down_sync(0xFFFFFFFFu, nn, off);
    }
    if (lane == 0) {
        red[warp][0] = ap; red[warp][1] = an; red[warp][2] = aa;
        red[warp][3] = pp; red[warp][4] = nn;
    }
    __syncthreads();

    if (t == 0) {
        const float sap = red[0][0] + red[1][0];
        const float san = red[0][1] + red[1][1];
        const float saa = red[0][2] + red[1][2];
        const float spp = red[0][3] + red[1][3];
        const float snn = red[0][4] + red[1][4];

        const float na = fmaxf(sqrtf(saa), EPS);
        const float np = fmaxf(sqrtf(spp), EPS);
        const float nq = fmaxf(sqrtf(snn), EPS);
        const float pos_sim = (sap / (na * np)) / TEMPERATURE;
        const float neg_sim = (san / (na * nq)) / TEMPERATURE;
        const float d = neg_sim - pos_sim;
        g_per_sample[s] = fmaxf(d, 0.f) + log1pf(expf(-fabsf(d)));

        __threadfence();                          // publish before signaling
        const int prev = atomicAdd(&g_counter, 1);
        is_last = (prev == B_SZ - 1) ? 1 : 0;
    }
    __syncthreads();

    // Last-arriving block performs the deterministic final mean.
    if (is_last && warp == 0) {
        // Fixed summation tree: identical result regardless of arrival order.
        float v = __ldcg(&g_per_sample[lane]) + __ldcg(&g_per_sample[lane + 32]);
        #pragma unroll
        for (int off = 16; off > 0; off >>= 1)
            v += __shfl_down_sync(0xFFFFFFFFu, v, off);
        if (lane == 0) {
            out[0] = v * (1.0f / (float)B_SZ);
            atomicExch(&g_counter, 0);            // reset for next graph replay
        }
    }
}

extern "C" void kernel_launch(void* const* d_in, const int* in_sizes, int n_in,
                              void* d_out, int out_size) {
    const float* emb           = (const float*)d_in[0];
    // d_in[1] = graph_labels (unused by the loss)
    const int*   anchor_idx    = (const int*)d_in[2];
    const int*   pos_idx       = (const int*)d_in[3];
    const int*   neg_graph_idx = (const int*)d_in[4];
    const int*   neg_node_idx  = (const int*)d_in[5];
    float*       out           = (float*)d_out;

    graph_contrastive_loss_kernel<<<B_SZ, 64>>>(
        emb, anchor_idx, pos_idx, neg_graph_idx, neg_node_idx, out);
}